// round 6
// baseline (speedup 1.0000x reference)
#include <cuda_runtime.h>
#include <cuda_bf16.h>

#define BB 8
#define NN 2048
#define BIGF 1e30f

// chamfer shape
#define TB     256
#define QPT    2
#define QCHUNK (QPT * TB)        // 512 queries per block
#define GQ     (NN / QCHUNK)     // 4 (covers cnt up to 2048)
#define RSPLIT 16                // cnt-relative ref chunks
#define RTILE  128               // max rn = ceil(2048/16)
#define GZ     (2 * BB)          // 16 tasks
#define ARR_PER_TASK (GQ * RSPLIT)   // 64 arrivals per task

// Scratch (allocation-free). Points stored transformed: (x+y, x-y, z, 0)
// g_valid[0] = clean (points+target), g_valid[1] = predp (points+pred)
__device__ __align__(16) float4       g_valid[2][BB][NN];
__device__ __align__(16) unsigned int g_minbits[2][BB][NN];
__device__ int          g_cnt[BB];          // zero at load; reset by last block
__device__ float        g_l1part[128];
__device__ unsigned int g_done_task[GZ];    // hierarchical arrive, level 1
__device__ unsigned int g_done;             // level 2

// ---------------------------------------------------------------------------
// Kernel 1: prep — 128 blocks x 128 threads, one point per thread.
// ---------------------------------------------------------------------------
__global__ void __launch_bounds__(128)
prep_kernel(const float* __restrict__ pred,
            const float* __restrict__ target,
            const int*   __restrict__ mask,
            const float* __restrict__ points) {
    int bid = blockIdx.x, tid = threadIdx.x;
    int b = bid >> 4, s = bid & 15;
    int n  = s * 128 + tid;
    int gi = b * NN + n;

    const float* pp = pred   + gi * 3;
    const float* tt = target + gi * 3;
    const float* xx = points + gi * 3;
    float p0 = pp[0], p1 = pp[1], p2 = pp[2];
    float t0 = tt[0], t1 = tt[1], t2 = tt[2];
    float x0 = xx[0], x1 = xx[1], x2 = xx[2];
    int m = mask[gi];

    const unsigned bigbits = __float_as_uint(BIGF);
    g_minbits[0][b][n] = bigbits;
    g_minbits[1][b][n] = bigbits;

    float c0 = x0 + t0, c1 = x1 + t1, c2 = x2 + t2;   // clean
    float q0 = x0 + p0, q1 = x1 + p1, q2 = x2 + p2;   // predp
    float l1 = 0.f;

    __shared__ int sh_cnt, sh_base;
    if (tid == 0) sh_cnt = 0;
    __syncthreads();
    int klocal = -1;
    if (m) {
        l1 = fabsf(p0 - t0) + fabsf(p1 - t1) + fabsf(p2 - t2);
        klocal = atomicAdd(&sh_cnt, 1);
    }
    __syncthreads();
    if (tid == 0) sh_base = atomicAdd(&g_cnt[b], sh_cnt);

    __shared__ float wsum[4];
#pragma unroll
    for (int o = 16; o > 0; o >>= 1) l1 += __shfl_down_sync(0xffffffffu, l1, o);
    if ((tid & 31) == 0) wsum[tid >> 5] = l1;
    __syncthreads();
    if (tid == 0)
        g_l1part[bid] = wsum[0] + wsum[1] + wsum[2] + wsum[3];

    if (m) {
        int k = sh_base + klocal;
        g_valid[0][b][k] = make_float4(c0 + c1, c0 - c1, c2, 0.f);
        g_valid[1][b][k] = make_float4(q0 + q1, q0 - q1, q2, 0.f);
    }
}

// ---------------------------------------------------------------------------
// Kernel 2: chamfer, grid (GQ, RSPLIT, GZ) = (4, 16, 16) = 1024 blocks, TB=256.
// |dx|+|dy|+|dz| == max(|du|,|dv|) + |dz| with (u,v) = (x+y, x-y).
// Pure scalar registers in the hot loop; last block finalizes.
// ---------------------------------------------------------------------------
__global__ void __launch_bounds__(TB)
chamfer_kernel(float* __restrict__ out) {
    int tid  = threadIdx.x;
    int task = blockIdx.z;
    int b    = task >> 1;
    int dir  = task & 1;              // 0: clean->pred, 1: pred->clean
    int cnt  = g_cnt[b];

    __shared__ float4 tile[RTILE];
    int q_lo = blockIdx.x * QCHUNK;
    int rn   = (cnt + RSPLIT - 1) / RSPLIT;   // <= 128
    int r_lo = blockIdx.y * rn;
    int rlen = min(rn, cnt - r_lo);

    if (q_lo < cnt && rlen > 0) {
        const float4* __restrict__ Q = g_valid[dir][b];
        const float4* __restrict__ R = g_valid[dir ^ 1][b];

        if (tid < RTILE)
            tile[tid] = (tid < rlen) ? R[r_lo + tid]
                                     : make_float4(BIGF, BIGF, BIGF, 0.f);

        int qi1 = q_lo + tid;             // < NN always
        int qi2 = q_lo + TB + tid;        // < NN always
        float4 a = Q[qi1];                // garbage beyond cnt: computed, not stored
        float4 c = Q[qi2];
        float ax = a.x, ay = a.y, az = a.z;
        float cx = c.x, cy = c.y, cz = c.z;
        float mn1 = BIGF, mn2 = BIGF;
        __syncthreads();

#pragma unroll 4
        for (int j = 0; j < rlen; ++j) {
            float4 y = tile[j];           // uniform LDS.128 broadcast
            float d  = fmaxf(fabsf(ax - y.x), fabsf(ay - y.y)) + fabsf(az - y.z);
            mn1 = fminf(mn1, d);
            float e  = fmaxf(fabsf(cx - y.x), fabsf(cy - y.y)) + fabsf(cz - y.z);
            mn2 = fminf(mn2, e);
        }

        if (qi1 < cnt) atomicMin(&g_minbits[dir][b][qi1], __float_as_uint(mn1));
        if (qi2 < cnt) atomicMin(&g_minbits[dir][b][qi2], __float_as_uint(mn2));
    }

    // -------- hierarchical arrive; globally-last block finalizes --------
    __threadfence();
    __syncthreads();
    __shared__ int is_last;
    if (tid == 0) {
        is_last = 0;
        if (atomicAdd(&g_done_task[task], 1u) == ARR_PER_TASK - 1) {
            __threadfence();
            is_last = (atomicAdd(&g_done, 1u) == GZ - 1);
        }
    }
    __syncthreads();
    if (!is_last) return;

    // -------- finalize (one block, vectorized) --------
    float acc = 0.f;                         // sum_b (S1[b]+S2[b]) / cnt[b]
    for (int bb = 0; bb < BB; ++bb) {
        int c = g_cnt[bb];
        const uint4* __restrict__ p0 = (const uint4*)g_minbits[0][bb];
        const uint4* __restrict__ p1 = (const uint4*)g_minbits[1][bb];
        int nv = c >> 2;
        float s0 = 0.f, s1 = 0.f;
        for (int k = tid; k < nv; k += TB) {
            uint4 u = p0[k], d = p1[k];
            s0 += (__uint_as_float(u.x) + __uint_as_float(u.y))
                + (__uint_as_float(u.z) + __uint_as_float(u.w));
            s1 += (__uint_as_float(d.x) + __uint_as_float(d.y))
                + (__uint_as_float(d.z) + __uint_as_float(d.w));
        }
        if (tid < (c & 3)) {
            int k = (c & ~3) + tid;
            s0 += __uint_as_float(g_minbits[0][bb][k]);
            s1 += __uint_as_float(g_minbits[1][bb][k]);
        }
        acc += (s0 + s1) / (float)c;
    }
    float l1p = (tid < 128) ? g_l1part[tid] : 0.f;

    __shared__ float wa[8], wl[8];
#pragma unroll
    for (int o = 16; o > 0; o >>= 1) {
        acc += __shfl_down_sync(0xffffffffu, acc, o);
        l1p += __shfl_down_sync(0xffffffffu, l1p, o);
    }
    if ((tid & 31) == 0) { wa[tid >> 5] = acc; wl[tid >> 5] = l1p; }
    __syncthreads();
    if (tid == 0) {
        float cdsum = 0.f, l1num = 0.f;
#pragma unroll
        for (int i = 0; i < 8; ++i) { cdsum += wa[i]; l1num += wl[i]; }
        int msum = 0;
#pragma unroll
        for (int bb = 0; bb < BB; ++bb) msum += g_cnt[bb];
        float l1 = l1num / 3.0f / (float)msum;
        float cd = cdsum / (float)BB;
        out[0] = l1 + expf(-l1) * cd;
        g_done = 0;                          // reset for next graph replay
    }
    if (tid < BB)  g_cnt[tid] = 0;
    if (tid < GZ)  g_done_task[tid] = 0;
}

// ---------------------------------------------------------------------------
extern "C" void kernel_launch(void* const* d_in, const int* in_sizes, int n_in,
                              void* d_out, int out_size) {
    const float* pred   = (const float*)d_in[0];
    const float* target = (const float*)d_in[1];
    const int*   mask   = (const int*)  d_in[2];
    const float* points = (const float*)d_in[3];
    float* out = (float*)d_out;

    prep_kernel<<<128, 128>>>(pred, target, mask, points);

    dim3 grid(GQ, RSPLIT, GZ);   // (4, 16, 16)
    chamfer_kernel<<<grid, TB>>>(out);
}

// round 7
// speedup vs baseline: 1.0892x; 1.0892x over previous
#include <cuda_runtime.h>
#include <cuda_bf16.h>

#define BB 8
#define NN 2048
#define BIGF 1e30f

// chamfer shape (R5's best-measured geometry)
#define TB     128
#define QPT    4
#define QCHUNK (QPT * TB)        // 512 queries per block
#define GQ     (NN / QCHUNK)     // 4
#define RSPLIT 32                // cnt-relative ref chunks
#define RTILE  64                // max rn = ceil(2048/32)
#define GZ     (2 * BB)          // 16 tasks
#define ARR_PER_TASK (GQ * RSPLIT)   // 128 arrivals per task

// Scratch (allocation-free). Points stored transformed: (x+y, x-y, z, 0)
// g_valid[0] = clean (points+target), g_valid[1] = predp (points+pred)
__device__ __align__(16) float4       g_valid[2][BB][NN];
__device__ __align__(16) unsigned int g_minbits[2][BB][NN];
__device__ int          g_cnt[BB];          // zero at load; reset by last block
__device__ float        g_l1part[128];
__device__ float        g_tasksum[GZ];      // per-(dir,b) sum of mins
__device__ unsigned int g_done_task[GZ];    // hierarchical arrive, level 1
__device__ unsigned int g_done;             // level 2

// ---------------------------------------------------------------------------
// Kernel 1: prep — 128 blocks x 128 threads, one point per thread.
// ---------------------------------------------------------------------------
__global__ void __launch_bounds__(128)
prep_kernel(const float* __restrict__ pred,
            const float* __restrict__ target,
            const int*   __restrict__ mask,
            const float* __restrict__ points) {
    int bid = blockIdx.x, tid = threadIdx.x;
    int b = bid >> 4, s = bid & 15;
    int n  = s * 128 + tid;
    int gi = b * NN + n;

    const float* pp = pred   + gi * 3;
    const float* tt = target + gi * 3;
    const float* xx = points + gi * 3;
    float p0 = pp[0], p1 = pp[1], p2 = pp[2];
    float t0 = tt[0], t1 = tt[1], t2 = tt[2];
    float x0 = xx[0], x1 = xx[1], x2 = xx[2];
    int m = mask[gi];

    const unsigned bigbits = __float_as_uint(BIGF);
    g_minbits[0][b][n] = bigbits;
    g_minbits[1][b][n] = bigbits;

    float c0 = x0 + t0, c1 = x1 + t1, c2 = x2 + t2;   // clean
    float q0 = x0 + p0, q1 = x1 + p1, q2 = x2 + p2;   // predp
    float l1 = 0.f;

    __shared__ int sh_cnt, sh_base;
    if (tid == 0) sh_cnt = 0;
    __syncthreads();
    int klocal = -1;
    if (m) {
        l1 = fabsf(p0 - t0) + fabsf(p1 - t1) + fabsf(p2 - t2);
        klocal = atomicAdd(&sh_cnt, 1);
    }
    __syncthreads();
    if (tid == 0) sh_base = atomicAdd(&g_cnt[b], sh_cnt);

    __shared__ float wsum[4];
#pragma unroll
    for (int o = 16; o > 0; o >>= 1) l1 += __shfl_down_sync(0xffffffffu, l1, o);
    if ((tid & 31) == 0) wsum[tid >> 5] = l1;
    __syncthreads();
    if (tid == 0)
        g_l1part[bid] = wsum[0] + wsum[1] + wsum[2] + wsum[3];

    if (m) {
        int k = sh_base + klocal;
        g_valid[0][b][k] = make_float4(c0 + c1, c0 - c1, c2, 0.f);
        g_valid[1][b][k] = make_float4(q0 + q1, q0 - q1, q2, 0.f);
    }
}

// ---------------------------------------------------------------------------
// Kernel 2: chamfer, grid (4, 32, 16) = 2048 blocks, TB=128, 4 queries/thread.
// |dx|+|dy|+|dz| == max(|du|,|dv|) + |dz| with (u,v) = (x+y, x-y).
// Named scalar registers only; per-task tail reduction; global-last combines.
// ---------------------------------------------------------------------------
__global__ void __launch_bounds__(TB)
chamfer_kernel(float* __restrict__ out) {
    int tid  = threadIdx.x;
    int task = blockIdx.z;
    int b    = task >> 1;
    int dir  = task & 1;              // 0: clean->pred, 1: pred->clean
    int cnt  = g_cnt[b];

    __shared__ float4 tile[RTILE];
    int q_lo = blockIdx.x * QCHUNK;
    int rn   = (cnt + RSPLIT - 1) / RSPLIT;   // <= 64
    int r_lo = blockIdx.y * rn;
    int rlen = min(rn, cnt - r_lo);

    if (q_lo < cnt && rlen > 0) {
        const float4* __restrict__ Q = g_valid[dir][b];
        const float4* __restrict__ R = g_valid[dir ^ 1][b];

        if (tid < RTILE)
            tile[tid] = (tid < rlen) ? R[r_lo + tid]
                                     : make_float4(BIGF, BIGF, BIGF, 0.f);

        int qi0 = q_lo + tid;                 // all < NN by construction
        int qi1 = qi0 + TB;
        int qi2 = qi0 + 2 * TB;
        int qi3 = qi0 + 3 * TB;
        float4 v0 = Q[qi0], v1 = Q[qi1], v2 = Q[qi2], v3 = Q[qi3];
        float qx0 = v0.x, qy0 = v0.y, qz0 = v0.z;
        float qx1 = v1.x, qy1 = v1.y, qz1 = v1.z;
        float qx2 = v2.x, qy2 = v2.y, qz2 = v2.z;
        float qx3 = v3.x, qy3 = v3.y, qz3 = v3.z;
        float mn0 = BIGF, mn1 = BIGF, mn2 = BIGF, mn3 = BIGF;
        __syncthreads();

#pragma unroll 4
        for (int j = 0; j < rlen; ++j) {
            float4 y = tile[j];               // uniform LDS.128 broadcast
            float d0 = fmaxf(fabsf(qx0 - y.x), fabsf(qy0 - y.y)) + fabsf(qz0 - y.z);
            mn0 = fminf(mn0, d0);
            float d1 = fmaxf(fabsf(qx1 - y.x), fabsf(qy1 - y.y)) + fabsf(qz1 - y.z);
            mn1 = fminf(mn1, d1);
            float d2 = fmaxf(fabsf(qx2 - y.x), fabsf(qy2 - y.y)) + fabsf(qz2 - y.z);
            mn2 = fminf(mn2, d2);
            float d3 = fmaxf(fabsf(qx3 - y.x), fabsf(qy3 - y.y)) + fabsf(qz3 - y.z);
            mn3 = fminf(mn3, d3);
        }

        unsigned int* __restrict__ M = g_minbits[dir][b];
        if (qi0 < cnt) atomicMin(&M[qi0], __float_as_uint(mn0));
        if (qi1 < cnt) atomicMin(&M[qi1], __float_as_uint(mn1));
        if (qi2 < cnt) atomicMin(&M[qi2], __float_as_uint(mn2));
        if (qi3 < cnt) atomicMin(&M[qi3], __float_as_uint(mn3));
    }

    // -------- hierarchical arrive --------
    __threadfence();
    __syncthreads();
    __shared__ int task_last;
    if (tid == 0)
        task_last = (atomicAdd(&g_done_task[task], 1u) == ARR_PER_TASK - 1);
    __syncthreads();
    if (!task_last) return;

    // -------- per-task tail: reduce this (dir,b) min array to one scalar ----
    __threadfence();                          // order: see all atomicMin results
    {
        const uint4* __restrict__ p = (const uint4*)g_minbits[dir][b];
        int nv = cnt >> 2;
        float s = 0.f;
        for (int k = tid; k < nv; k += TB) {
            uint4 u = p[k];
            s += (__uint_as_float(u.x) + __uint_as_float(u.y))
               + (__uint_as_float(u.z) + __uint_as_float(u.w));
        }
        if (tid < (cnt & 3))
            s += __uint_as_float(g_minbits[dir][b][(cnt & ~3) + tid]);

        __shared__ float wsum[4];
#pragma unroll
        for (int o = 16; o > 0; o >>= 1) s += __shfl_down_sync(0xffffffffu, s, o);
        if ((tid & 31) == 0) wsum[tid >> 5] = s;
        __syncthreads();
        if (tid == 0)
            g_tasksum[task] = wsum[0] + wsum[1] + wsum[2] + wsum[3];
    }

    // -------- global arrive; last task-block combines --------
    __threadfence();
    __syncthreads();
    __shared__ int is_last;
    if (tid == 0)
        is_last = (atomicAdd(&g_done, 1u) == GZ - 1);
    __syncthreads();
    if (!is_last) return;

    __threadfence();
    float l1p = g_l1part[tid];                // 128 partials, TB == 128
    __shared__ float wl[4];
#pragma unroll
    for (int o = 16; o > 0; o >>= 1) l1p += __shfl_down_sync(0xffffffffu, l1p, o);
    if ((tid & 31) == 0) wl[tid >> 5] = l1p;
    __syncthreads();
    if (tid == 0) {
        float cdsum = 0.f;
#pragma unroll
        for (int t = 0; t < GZ; ++t)
            cdsum += g_tasksum[t] / (float)g_cnt[t >> 1];
        float l1num = wl[0] + wl[1] + wl[2] + wl[3];
        int msum = 0;
#pragma unroll
        for (int bb = 0; bb < BB; ++bb) msum += g_cnt[bb];
        float l1 = l1num / 3.0f / (float)msum;
        float cd = cdsum / (float)BB;
        out[0] = l1 + expf(-l1) * cd;
        g_done = 0;                           // reset for next graph replay
    }
    __syncthreads();
    if (tid < BB)  g_cnt[tid] = 0;
    if (tid < GZ)  g_done_task[tid] = 0;
}

// ---------------------------------------------------------------------------
extern "C" void kernel_launch(void* const* d_in, const int* in_sizes, int n_in,
                              void* d_out, int out_size) {
    const float* pred   = (const float*)d_in[0];
    const float* target = (const float*)d_in[1];
    const int*   mask   = (const int*)  d_in[2];
    const float* points = (const float*)d_in[3];
    float* out = (float*)d_out;

    prep_kernel<<<128, 128>>>(pred, target, mask, points);

    dim3 grid(GQ, RSPLIT, GZ);   // (4, 32, 16)
    chamfer_kernel<<<grid, TB>>>(out);
}